// round 17
// baseline (speedup 1.0000x reference)
#include <cuda_runtime.h>
#include <cuda_fp16.h>
#include <mma.h>

using namespace nvcuda;

// Problem constants (fixed by the dataset)
#define NMAX 50000
#define EMAX 800000
#define DOUT 128
#define DIN 128
#define NEG_SLOPE 0.2f
#define WCAP 128   // per-warp staged edges in k_node

// ---------------- scratch (device globals; no allocation allowed) ----------
__device__ __half g_xwh[NMAX * DOUT];     // 12.8 MB, fp16 xw (k_node gather)
__device__ float  g_asrc[NMAX];
__device__ float  g_adst[NMAX];
__device__ int    g_cnt[NMAX];            // per-dst edge count (self-cleaning)
__device__ int    g_rowstart[NMAX + 1];   // CSR row offsets
__device__ int    g_cursor[NMAX];         // scatter cursors
__device__ int    g_csr_src[EMAX];        // CSR: src per edge, grouped by dst
__device__ int    g_bsum[64];             // scan: per-block totals
__device__ int    g_boff[64];             // scan: per-block exclusive offsets
__device__ int    g_total;                // scan: grand total
__device__ int    g_done;                 // scan: last-block counter (self-clean)

// ---------------- block-local edge-index dtype detection --------------------
// int64 little-endian with ids < 2^31 -> odd 32-bit words all zero.
__device__ __forceinline__ int detect_is64_block(const int* __restrict__ w,
                                                 int* sh) {
    if (threadIdx.x == 0) {
        int odd_or = 0;
#pragma unroll
        for (int j = 0; j < 16; j++) odd_or |= w[2 * j + 1];
        *sh = (odd_or == 0) ? 1 : 0;
    }
    __syncthreads();
    return *sh;
}

// -------- 1) GEMM: xw = x @ W  (tf32 tensor cores, BM=128 x N=128) ---------
//            + fused attention logits; stores xw as fp16
__global__ __launch_bounds__(256)
void k_gemm(const float* __restrict__ x, const float* __restrict__ W,
            const float* __restrict__ att_src, const float* __restrict__ att_dst,
            int nrows) {
    __shared__ float As[128][36];      // x tile  [m][k], BK=32 (+pad)
    __shared__ float Ws[32][132];      // W tile  [k][n]      (+pad)
    __shared__ float stg[8][16][20];   // per-warp 16x16 frag staging (ld=20)
    __shared__ float s_src[128], s_dst[128];
    __shared__ float sas[128], sad[128];

    int tid = threadIdx.x;
    int lane = tid & 31;
    int wid = tid >> 5;
    int wm = wid >> 2;     // 0..1 -> rows wm*64
    int wn = wid & 3;      // 0..3 -> cols wn*32
    int row0 = blockIdx.x * 128;

    if (tid < 128) {
        s_src[tid] = 0.0f; s_dst[tid] = 0.0f;
        sas[tid] = att_src[tid]; sad[tid] = att_dst[tid];
    }

    wmma::fragment<wmma::accumulator, 16, 16, 8, float> acc[4][2];
#pragma unroll
    for (int mt = 0; mt < 4; mt++)
#pragma unroll
        for (int nt = 0; nt < 2; nt++) wmma::fill_fragment(acc[mt][nt], 0.0f);

    for (int k0 = 0; k0 < DIN; k0 += 32) {
#pragma unroll
        for (int p = 0; p < 4; p++) {
            int fi = tid + 256 * p;
            int r = fi >> 3;            // 0..127
            int q = fi & 7;             // float4 along k
            float4 v = make_float4(0.f, 0.f, 0.f, 0.f);
            int gr = row0 + r;
            if (gr < nrows)
                v = *reinterpret_cast<const float4*>(x + (size_t)gr * DIN + k0 + 4 * q);
            As[r][4 * q + 0] = v.x; As[r][4 * q + 1] = v.y;
            As[r][4 * q + 2] = v.z; As[r][4 * q + 3] = v.w;
        }
#pragma unroll
        for (int p = 0; p < 4; p++) {
            int fi = tid + 256 * p;
            int kr = fi >> 5;           // 0..31
            int q = (fi & 31) * 4;
            float4 v = *reinterpret_cast<const float4*>(W + (size_t)(k0 + kr) * DOUT + q);
            Ws[kr][q + 0] = v.x; Ws[kr][q + 1] = v.y;
            Ws[kr][q + 2] = v.z; Ws[kr][q + 3] = v.w;
        }
        __syncthreads();

#pragma unroll
        for (int kk = 0; kk < 32; kk += 8) {
            wmma::fragment<wmma::matrix_a, 16, 16, 8, wmma::precision::tf32, wmma::row_major> af[4];
            wmma::fragment<wmma::matrix_b, 16, 16, 8, wmma::precision::tf32, wmma::row_major> bf[2];
#pragma unroll
            for (int mt = 0; mt < 4; mt++) {
                wmma::load_matrix_sync(af[mt], &As[wm * 64 + mt * 16][kk], 36);
#pragma unroll
                for (int i = 0; i < af[mt].num_elements; i++)
                    af[mt].x[i] = wmma::__float_to_tf32(af[mt].x[i]);
            }
#pragma unroll
            for (int nt = 0; nt < 2; nt++) {
                wmma::load_matrix_sync(bf[nt], &Ws[kk][wn * 32 + nt * 16], 132);
#pragma unroll
                for (int i = 0; i < bf[nt].num_elements; i++)
                    bf[nt].x[i] = wmma::__float_to_tf32(bf[nt].x[i]);
            }
#pragma unroll
            for (int mt = 0; mt < 4; mt++)
#pragma unroll
                for (int nt = 0; nt < 2; nt++)
                    wmma::mma_sync(acc[mt][nt], af[mt], bf[nt], acc[mt][nt]);
        }
        __syncthreads();
    }

    // epilogue: per 16x16 tile -> smem -> fp16 store + logit partials
    int r = lane >> 1;         // 0..15 row within tile
    int h = lane & 1;          // 0/1 column half (8 cols)
#pragma unroll
    for (int mt = 0; mt < 4; mt++) {
#pragma unroll
        for (int nt = 0; nt < 2; nt++) {
            __syncwarp();
            wmma::store_matrix_sync(&stg[wid][0][0], acc[mt][nt], 20, wmma::mem_row_major);
            __syncwarp();
            int br = wm * 64 + mt * 16 + r;       // row within block
            int gr = row0 + br;
            int c0 = wn * 32 + nt * 16 + h * 8;   // global col
            float4 v0 = *reinterpret_cast<float4*>(&stg[wid][r][h * 8]);
            float4 v1 = *reinterpret_cast<float4*>(&stg[wid][r][h * 8 + 4]);
            float ps = v0.x * sas[c0]     + v0.y * sas[c0 + 1] + v0.z * sas[c0 + 2] + v0.w * sas[c0 + 3]
                     + v1.x * sas[c0 + 4] + v1.y * sas[c0 + 5] + v1.z * sas[c0 + 6] + v1.w * sas[c0 + 7];
            float pd = v0.x * sad[c0]     + v0.y * sad[c0 + 1] + v0.z * sad[c0 + 2] + v0.w * sad[c0 + 3]
                     + v1.x * sad[c0 + 4] + v1.y * sad[c0 + 5] + v1.z * sad[c0 + 6] + v1.w * sad[c0 + 7];
            atomicAdd(&s_src[br], ps);
            atomicAdd(&s_dst[br], pd);
            if (gr < nrows) {
                __half2 hh[4];
                hh[0] = __float22half2_rn(make_float2(v0.x, v0.y));
                hh[1] = __float22half2_rn(make_float2(v0.z, v0.w));
                hh[2] = __float22half2_rn(make_float2(v1.x, v1.y));
                hh[3] = __float22half2_rn(make_float2(v1.z, v1.w));
                *reinterpret_cast<uint4*>(&g_xwh[(size_t)gr * DOUT + c0]) =
                    *reinterpret_cast<uint4*>(hh);
            }
        }
    }
    __syncthreads();
    if (tid < 128) {
        int gr = row0 + tid;
        if (gr < nrows) { g_asrc[gr] = s_src[tid]; g_adst[gr] = s_dst[tid]; }
    }
}

// ---------------- 2) histogram of destinations (inline dtype detect) -------
__global__ void k_count(const int* __restrict__ ei, int E) {
    __shared__ int sh64;
    int is64 = detect_is64_block(ei, &sh64);
    int i0 = (blockIdx.x * blockDim.x + threadIdx.x) * 4;
    if (i0 >= E) return;
    if (i0 + 4 <= E) {
        int d0, d1, d2, d3;
        if (is64) {
            int4 a = *reinterpret_cast<const int4*>(&ei[2 * ((size_t)E + i0)]);
            int4 b = *reinterpret_cast<const int4*>(&ei[2 * ((size_t)E + i0) + 4]);
            d0 = a.x; d1 = a.z; d2 = b.x; d3 = b.z;
        } else {
            int4 a = *reinterpret_cast<const int4*>(&ei[E + i0]);
            d0 = a.x; d1 = a.y; d2 = a.z; d3 = a.w;
        }
        atomicAdd(&g_cnt[d0], 1);
        atomicAdd(&g_cnt[d1], 1);
        atomicAdd(&g_cnt[d2], 1);
        atomicAdd(&g_cnt[d3], 1);
    } else {
        for (int i = i0; i < E; i++) {
            int d = is64 ? ei[2 * ((size_t)E + i)] : ei[E + i];
            atomicAdd(&g_cnt[d], 1);
        }
    }
}

// ------- 3) scan: per-block scan + fused top-level scan (last block) --------
__global__ __launch_bounds__(256)
void k_scan1(int n, int nb) {
    __shared__ int warp_sums[8];
    __shared__ int amLast;
    int blk = blockIdx.x;
    int t = threadIdx.x;
    int lane = t & 31, wid = t >> 5;
    int base = blk * 1024 + t * 4;

    int v[4];
#pragma unroll
    for (int i = 0; i < 4; i++) {
        int idx = base + i;
        if (idx < n) { v[i] = g_cnt[idx]; g_cnt[idx] = 0; }  // self-cleaning
        else v[i] = 0;
    }
    int local = v[0] + v[1] + v[2] + v[3];

    int inc = local;
#pragma unroll
    for (int off = 1; off < 32; off <<= 1) {
        int x = __shfl_up_sync(0xFFFFFFFFu, inc, off);
        if (lane >= off) inc += x;
    }
    if (lane == 31) warp_sums[wid] = inc;
    __syncthreads();
    if (wid == 0) {
        int ws = (lane < 8) ? warp_sums[lane] : 0;
#pragma unroll
        for (int off = 1; off < 8; off <<= 1) {
            int x = __shfl_up_sync(0xFFFFFFFFu, ws, off);
            if (lane >= off) ws += x;
        }
        if (lane < 8) warp_sums[lane] = ws;
    }
    __syncthreads();

    int run = inc - local + ((wid > 0) ? warp_sums[wid - 1] : 0);
#pragma unroll
    for (int i = 0; i < 4; i++) {
        int idx = base + i;
        if (idx < n) g_rowstart[idx] = run;
        run += v[i];
    }
    if (t == 255) g_bsum[blk] = warp_sums[7];

    // fused top-level scan: last block to finish does scan2's work
    __threadfence();
    __syncthreads();
    if (t == 0) amLast = (atomicAdd(&g_done, 1) == nb - 1) ? 1 : 0;
    __syncthreads();
    if (amLast && wid == 0) {
        int v0 = (2 * lane < nb)     ? g_bsum[2 * lane]     : 0;
        int v1 = (2 * lane + 1 < nb) ? g_bsum[2 * lane + 1] : 0;
        int loc = v0 + v1;
        int in2 = loc;
#pragma unroll
        for (int off = 1; off < 32; off <<= 1) {
            int x = __shfl_up_sync(0xFFFFFFFFu, in2, off);
            if (lane >= off) in2 += x;
        }
        int excl = in2 - loc;
        if (2 * lane < nb)     g_boff[2 * lane]     = excl;
        if (2 * lane + 1 < nb) g_boff[2 * lane + 1] = excl + v0;
        if (lane == 31) { g_total = in2; g_done = 0; }  // reset for replay
    }
}

__global__ void k_scan3(int n) {
    int i = blockIdx.x * blockDim.x + threadIdx.x;
    if (i < n) {
        int r = g_rowstart[i] + g_boff[i >> 10];
        g_rowstart[i] = r;
        g_cursor[i] = r;
    }
    if (i == 0) g_rowstart[n] = g_total;
}

// ---------------- 4) scatter edges into CSR (inline dtype detect) -----------
__global__ void k_scatter(const int* __restrict__ ei, int E) {
    __shared__ int sh64;
    int is64 = detect_is64_block(ei, &sh64);
    int i0 = (blockIdx.x * blockDim.x + threadIdx.x) * 4;
    if (i0 >= E) return;
    if (i0 + 4 <= E) {
        int s0, s1, s2, s3, d0, d1, d2, d3;
        if (is64) {
            int4 sa = *reinterpret_cast<const int4*>(&ei[2 * (size_t)i0]);
            int4 sb = *reinterpret_cast<const int4*>(&ei[2 * (size_t)i0 + 4]);
            int4 da = *reinterpret_cast<const int4*>(&ei[2 * ((size_t)E + i0)]);
            int4 db = *reinterpret_cast<const int4*>(&ei[2 * ((size_t)E + i0) + 4]);
            s0 = sa.x; s1 = sa.z; s2 = sb.x; s3 = sb.z;
            d0 = da.x; d1 = da.z; d2 = db.x; d3 = db.z;
        } else {
            int4 sa = *reinterpret_cast<const int4*>(&ei[i0]);
            int4 da = *reinterpret_cast<const int4*>(&ei[E + i0]);
            s0 = sa.x; s1 = sa.y; s2 = sa.z; s3 = sa.w;
            d0 = da.x; d1 = da.y; d2 = da.z; d3 = da.w;
        }
        g_csr_src[atomicAdd(&g_cursor[d0], 1)] = s0;
        g_csr_src[atomicAdd(&g_cursor[d1], 1)] = s1;
        g_csr_src[atomicAdd(&g_cursor[d2], 1)] = s2;
        g_csr_src[atomicAdd(&g_cursor[d3], 1)] = s3;
    } else {
        for (int i = i0; i < E; i++) {
            int s = is64 ? ei[2 * (size_t)i] : ei[i];
            int d = is64 ? ei[2 * ((size_t)E + i)] : ei[E + i];
            g_csr_src[atomicAdd(&g_cursor[d], 1)] = s;
        }
    }
}

// ------ 5) per-node softmax + aggregation + bias + ELU ----------------------
// One warp per node, split into two 16-lane halves; each half processes a
// different edge with one uint4 (16B) load per lane; halves merge via shfl.
__device__ __forceinline__ void accum8(float* acc, uint4 u, float a) {
    __half2* hp = reinterpret_cast<__half2*>(&u);
#pragma unroll
    for (int k = 0; k < 4; k++) {
        float2 f = __half22float2(hp[k]);
        acc[2 * k]     = fmaf(a, f.x, acc[2 * k]);
        acc[2 * k + 1] = fmaf(a, f.y, acc[2 * k + 1]);
    }
}

__global__ __launch_bounds__(256)
void k_node(float* __restrict__ out, const float* __restrict__ bias, int n) {
    __shared__ int   sh_src[8][WCAP];
    __shared__ float sh_ex[8][WCAP];

    int w = threadIdx.x >> 5;
    int d = blockIdx.x * 8 + w;
    if (d >= n) return;
    int l = threadIdx.x & 31;
    int h = l >> 4;        // half-warp (edge parity)
    int li = l & 15;       // lane within half -> cols li*8 .. li*8+7

    int row = g_rowstart[d];
    int end = g_rowstart[d + 1];
    int deg = end - row;
    float adv = g_adst[d];

    // phase 1: denom + stage (src, exp) into smem (full warp)
    float es = g_asrc[d] + adv;
    es = (es > 0.0f) ? es : NEG_SLOPE * es;
    float ex_self = __expf(es);
    float sum = 0.0f;
    for (int j = l; j < deg; j += 32) {
        int s = g_csr_src[row + j];
        float e = g_asrc[s] + adv;
        e = (e > 0.0f) ? e : NEG_SLOPE * e;
        float ex = __expf(e);
        sum += ex;
        if (j < WCAP) { sh_src[w][j] = s; sh_ex[w][j] = ex; }
    }
#pragma unroll
    for (int off = 16; off > 0; off >>= 1)
        sum += __shfl_xor_sync(0xFFFFFFFFu, sum, off);
    float inv = 1.0f / (sum + ex_self);
    __syncwarp();

    // phase 2: acc[8] covers cols li*8..li*8+7; half h takes edges j+h
    float acc[8];
#pragma unroll
    for (int k = 0; k < 8; k++) acc[k] = 0.0f;
    if (h == 0) {   // self loop counted once
        uint4 u = *reinterpret_cast<const uint4*>(&g_xwh[(size_t)d * DOUT + li * 8]);
        accum8(acc, u, ex_self * inv);
    }

    int m = (deg < WCAP) ? deg : WCAP;
    int j = 0;
    for (; j + 4 <= m; j += 4) {           // 4 edges per iter: 2 per half
        int e0 = j + h, e1 = j + 2 + h;
        int s0 = sh_src[w][e0], s1 = sh_src[w][e1];
        float a0 = sh_ex[w][e0] * inv, a1 = sh_ex[w][e1] * inv;
        uint4 u0 = *reinterpret_cast<const uint4*>(&g_xwh[(size_t)s0 * DOUT + li * 8]);
        uint4 u1 = *reinterpret_cast<const uint4*>(&g_xwh[(size_t)s1 * DOUT + li * 8]);
        accum8(acc, u0, a0);
        accum8(acc, u1, a1);
    }
    for (; j < m; j += 2) {                // pair tail
        int e0 = j + h;
        if (e0 < m) {
            int s = sh_src[w][e0];
            float a = sh_ex[w][e0] * inv;
            uint4 u = *reinterpret_cast<const uint4*>(&g_xwh[(size_t)s * DOUT + li * 8]);
            accum8(acc, u, a);
        }
    }
    for (int j2 = WCAP; j2 < deg; j2 += 2) {   // overflow (deg > WCAP)
        int e0 = j2 + h;
        if (e0 < deg) {
            int s = g_csr_src[row + e0];
            float e = g_asrc[s] + adv;
            e = (e > 0.0f) ? e : NEG_SLOPE * e;
            float a = __expf(e) * inv;
            uint4 u = *reinterpret_cast<const uint4*>(&g_xwh[(size_t)s * DOUT + li * 8]);
            accum8(acc, u, a);
        }
    }

    // merge halves: h0 += h1 (all lanes participate in the shuffle)
#pragma unroll
    for (int k = 0; k < 8; k++)
        acc[k] += __shfl_down_sync(0xFFFFFFFFu, acc[k], 16);

    if (h == 0) {
        float4 b0 = *reinterpret_cast<const float4*>(bias + li * 8);
        float4 b1 = *reinterpret_cast<const float4*>(bias + li * 8 + 4);
        float r[8] = {acc[0] + b0.x, acc[1] + b0.y, acc[2] + b0.z, acc[3] + b0.w,
                      acc[4] + b1.x, acc[5] + b1.y, acc[6] + b1.z, acc[7] + b1.w};
#pragma unroll
        for (int k = 0; k < 8; k++) r[k] = (r[k] > 0.0f) ? r[k] : expm1f(r[k]);
        *reinterpret_cast<float4*>(&out[(size_t)d * DOUT + li * 8]) =
            make_float4(r[0], r[1], r[2], r[3]);
        *reinterpret_cast<float4*>(&out[(size_t)d * DOUT + li * 8 + 4]) =
            make_float4(r[4], r[5], r[6], r[7]);
    }
}

// ---------------- launch ---------------------------------------------------
extern "C" void kernel_launch(void* const* d_in, const int* in_sizes, int n_in,
                              void* d_out, int out_size) {
    const float* x    = (const float*)d_in[0];
    const int*   ei   = (const int*)d_in[1];    // int32 words (int64 auto-detected)
    const float* W    = (const float*)d_in[2];
    const float* asv  = (const float*)d_in[3];
    const float* adv  = (const float*)d_in[4];
    const float* bias = (const float*)d_in[5];
    float* out = (float*)d_out;

    int n = in_sizes[0] / DIN;      // 50000
    int E = in_sizes[1] / 2;        // 800000
    int nb = (n + 1023) / 1024;     // scan blocks (49)

    int t = 256;
    k_gemm<<<(n + 127) / 128, 256>>>(x, W, asv, adv, n);
    k_count<<<(E + 4 * t - 1) / (4 * t), t>>>(ei, E);
    k_scan1<<<nb, 256>>>(n, nb);
    k_scan3<<<(n + t - 1) / t, t>>>(n);
    k_scatter<<<(E + 4 * t - 1) / (4 * t), t>>>(ei, E);
    k_node<<<(n + 7) / 8, t>>>(out, bias, n);
}